// round 1
// baseline (speedup 1.0000x reference)
#include <cuda_runtime.h>

#define FRAME_NUMBER 16
#define FRAME_SIZE   128
#define SAMPLE_NUM   16
#define NUM_EVENTS   1048576
#define EV_PER_FRAME (NUM_EVENTS / FRAME_NUMBER)      /* 65536 */
#define BINS         (FRAME_SIZE * FRAME_SIZE)        /* 16384 */
#define HIST         (2 * BINS)                       /* 32768 floats = 128 KB */

// Scratch: packed bin id (y*128 + x) per event. __device__ global (no allocs allowed).
__device__ int g_bins[NUM_EVENTS];

// ---------------------------------------------------------------------------
// Prepass: pack (x, y) -> bin, handling int64 OR int32 index dtype.
// Detection: view buffer as int32. If dtype is int64, words [N-1], [N-3], ...
// are the HIGH words of mid-range t values (~32768) -> all zero. If dtype is
// int32 those words are the tail of the SORTED t row (~65535) -> all nonzero.
// ---------------------------------------------------------------------------
__global__ void bins_kernel(const int* __restrict__ idx32) {
    const int i = blockIdx.x * blockDim.x + threadIdx.x;
    const bool is64 = (idx32[NUM_EVENTS - 1] == 0) &&
                      (idx32[NUM_EVENTS - 3] == 0) &&
                      (idx32[NUM_EVENTS - 5] == 0) &&
                      (idx32[NUM_EVENTS - 7] == 0);
    int x, y;
    if (is64) {
        // int64 rows: t=[0,N), x=[N,2N), y=[2N,3N); low word little-endian
        x = idx32[2 * (NUM_EVENTS + i)];
        y = idx32[2 * (2 * NUM_EVENTS + i)];
    } else {
        x = idx32[NUM_EVENTS + i];
        y = idx32[2 * NUM_EVENTS + i];
    }
    g_bins[i] = y * FRAME_SIZE + x;
}

// ---------------------------------------------------------------------------
// Main: one CTA per (frame, sample). Full 2x128x128 histogram in smem,
// smem atomics for scatter, coalesced float4 writeback.
// out[f, s, c, y, x] : flat = (f*S + s)*32768 + c*16384 + y*128 + x
// ---------------------------------------------------------------------------
__global__ __launch_bounds__(1024, 1)
void accum_kernel(const float* __restrict__ vals, float* __restrict__ out) {
    extern __shared__ float hist[];   // HIST floats
    const int f = blockIdx.x;
    const int s = blockIdx.y;

    #pragma unroll
    for (int i = threadIdx.x; i < HIST; i += 1024) hist[i] = 0.0f;
    __syncthreads();

    const float* __restrict__ v = vals + (size_t)s * NUM_EVENTS + (size_t)f * EV_PER_FRAME;
    const int*   __restrict__ b = g_bins + f * EV_PER_FRAME;

    const int t4 = threadIdx.x * 4;
    #pragma unroll
    for (int it = 0; it < EV_PER_FRAME / (1024 * 4); ++it) {   // 16 iterations
        const int idx = it * 4096 + t4;
        const float4 v4 = *reinterpret_cast<const float4*>(v + idx);
        const int4   b4 = *reinterpret_cast<const int4*>(b + idx);
        // channel 1 (pos) gets relu(v), channel 0 (neg) gets relu(-v).
        // Exactly one of the two is nonzero; adding +0 is a no-op, so fold
        // into a single atomic of |v| to the selected channel.
        atomicAdd(&hist[(v4.x > 0.0f ? BINS : 0) + b4.x], fabsf(v4.x));
        atomicAdd(&hist[(v4.y > 0.0f ? BINS : 0) + b4.y], fabsf(v4.y));
        atomicAdd(&hist[(v4.z > 0.0f ? BINS : 0) + b4.z], fabsf(v4.z));
        atomicAdd(&hist[(v4.w > 0.0f ? BINS : 0) + b4.w], fabsf(v4.w));
    }
    __syncthreads();

    float4* __restrict__ o =
        reinterpret_cast<float4*>(out + (size_t)(f * SAMPLE_NUM + s) * HIST);
    const float4* h4 = reinterpret_cast<const float4*>(hist);
    #pragma unroll
    for (int i = threadIdx.x; i < HIST / 4; i += 1024) o[i] = h4[i];
}

extern "C" void kernel_launch(void* const* d_in, const int* in_sizes, int n_in,
                              void* d_out, int out_size) {
    (void)in_sizes; (void)n_in; (void)out_size;
    const float* vals  = (const float*)d_in[0];
    const int*   idx32 = (const int*)d_in[1];   // raw view; dtype detected on device
    float*       out   = (float*)d_out;

    // 128 KB dynamic smem needs opt-in (idempotent; not a stream op, capture-safe)
    cudaFuncSetAttribute(accum_kernel,
                         cudaFuncAttributeMaxDynamicSharedMemorySize,
                         HIST * (int)sizeof(float));

    bins_kernel<<<NUM_EVENTS / 256, 256>>>(idx32);
    accum_kernel<<<dim3(FRAME_NUMBER, SAMPLE_NUM), 1024, HIST * sizeof(float)>>>(vals, out);
}

// round 2
// speedup vs baseline: 1.4662x; 1.4662x over previous
#include <cuda_runtime.h>

#define FRAME_NUMBER 16
#define FRAME_SIZE   128
#define SAMPLE_NUM   16
#define NUM_EVENTS   1048576
#define EV_PER_FRAME (NUM_EVENTS / FRAME_NUMBER)      /* 65536 */
#define BINS         (FRAME_SIZE * FRAME_SIZE)        /* 16384 */
#define HIST         (2 * BINS)                       /* 32768 floats = 128 KB */

// Scratch: packed bin id (y*128 + x) per event. __device__ global (no allocs allowed).
__device__ int g_bins[NUM_EVENTS];

// ---------------------------------------------------------------------------
// Prepass: pack (x, y) -> bin, handling int64 OR int32 index dtype.
// Detection: view buffer as int32. If dtype is int64, words [N-1],[N-3],... are
// HIGH words of mid-range sorted t values -> all zero. If int32, those words
// are the tail of the sorted t row (~65535) -> nonzero.
// Vectorized: each thread packs 4 events.
// ---------------------------------------------------------------------------
__global__ __launch_bounds__(256)
void bins_kernel(const int* __restrict__ idx32) {
    const int e = (blockIdx.x * blockDim.x + threadIdx.x) * 4;  // first event
    const bool is64 = (idx32[NUM_EVENTS - 1] == 0) &&
                      (idx32[NUM_EVENTS - 3] == 0) &&
                      (idx32[NUM_EVENTS - 5] == 0) &&
                      (idx32[NUM_EVENTS - 7] == 0);
    int4 out;
    if (is64) {
        const longlong2* __restrict__ px =
            reinterpret_cast<const longlong2*>(idx32) + (NUM_EVENTS + e) / 2;
        const longlong2* __restrict__ py =
            reinterpret_cast<const longlong2*>(idx32) + (2 * NUM_EVENTS + e) / 2;
        longlong2 x01 = px[0], x23 = px[1];
        longlong2 y01 = py[0], y23 = py[1];
        out.x = (int)y01.x * FRAME_SIZE + (int)x01.x;
        out.y = (int)y01.y * FRAME_SIZE + (int)x01.y;
        out.z = (int)y23.x * FRAME_SIZE + (int)x23.x;
        out.w = (int)y23.y * FRAME_SIZE + (int)x23.y;
    } else {
        const int4 x4 = *reinterpret_cast<const int4*>(idx32 + NUM_EVENTS + e);
        const int4 y4 = *reinterpret_cast<const int4*>(idx32 + 2 * NUM_EVENTS + e);
        out.x = y4.x * FRAME_SIZE + x4.x;
        out.y = y4.y * FRAME_SIZE + x4.y;
        out.z = y4.z * FRAME_SIZE + x4.z;
        out.w = y4.w * FRAME_SIZE + x4.w;
    }
    *reinterpret_cast<int4*>(g_bins + e) = out;
}

// ---------------------------------------------------------------------------
// Main: one CTA per (frame, sample). Full 2x128x128 f32 histogram in smem,
// smem atomics for scatter, coalesced float4 writeback.
// Software double-buffered: next iteration's loads issued before this
// iteration's 8 atomics, keeping the ATOMS pipe fed across DRAM latency.
// out[f, s, c, y, x] : flat = (f*S + s)*32768 + c*16384 + y*128 + x
// ---------------------------------------------------------------------------
#define TPB      1024
#define EV_PER_T 8                         /* events per thread per iter */
#define CHUNK    (TPB * EV_PER_T)          /* 8192 events per iter */
#define NITER    (EV_PER_FRAME / CHUNK)    /* 8 iterations */

__device__ __forceinline__ void scatter4(float* hist, float4 v4, int4 b4) {
    atomicAdd(&hist[(v4.x > 0.0f ? BINS : 0) + b4.x], fabsf(v4.x));
    atomicAdd(&hist[(v4.y > 0.0f ? BINS : 0) + b4.y], fabsf(v4.y));
    atomicAdd(&hist[(v4.z > 0.0f ? BINS : 0) + b4.z], fabsf(v4.z));
    atomicAdd(&hist[(v4.w > 0.0f ? BINS : 0) + b4.w], fabsf(v4.w));
}

__global__ __launch_bounds__(TPB, 1)
void accum_kernel(const float* __restrict__ vals, float* __restrict__ out) {
    extern __shared__ float hist[];   // HIST floats = 128 KB
    const int f = blockIdx.x;
    const int s = blockIdx.y;

    // zero histogram (float4 stores)
    {
        float4 z = make_float4(0.f, 0.f, 0.f, 0.f);
        float4* h4 = reinterpret_cast<float4*>(hist);
        #pragma unroll
        for (int i = threadIdx.x; i < HIST / 4; i += TPB) h4[i] = z;
    }
    __syncthreads();

    const float* __restrict__ v = vals + (size_t)s * NUM_EVENTS + (size_t)f * EV_PER_FRAME;
    const int*   __restrict__ b = g_bins + f * EV_PER_FRAME;

    const int t8 = threadIdx.x * EV_PER_T;

    // prologue: load chunk 0 (front-batched: 4 independent vector loads)
    float4 cv0 = *reinterpret_cast<const float4*>(v + t8);
    float4 cv1 = *reinterpret_cast<const float4*>(v + t8 + 4);
    int4   cb0 = *reinterpret_cast<const int4*>(b + t8);
    int4   cb1 = *reinterpret_cast<const int4*>(b + t8 + 4);

    #pragma unroll
    for (int it = 0; it < NITER; ++it) {
        float4 nv0, nv1; int4 nb0, nb1;
        if (it + 1 < NITER) {
            const int nidx = (it + 1) * CHUNK + t8;
            nv0 = *reinterpret_cast<const float4*>(v + nidx);
            nv1 = *reinterpret_cast<const float4*>(v + nidx + 4);
            nb0 = *reinterpret_cast<const int4*>(b + nidx);
            nb1 = *reinterpret_cast<const int4*>(b + nidx + 4);
        }
        scatter4(hist, cv0, cb0);
        scatter4(hist, cv1, cb1);
        if (it + 1 < NITER) {
            cv0 = nv0; cv1 = nv1; cb0 = nb0; cb1 = nb1;
        }
    }
    __syncthreads();

    // coalesced writeback
    float4* __restrict__ o =
        reinterpret_cast<float4*>(out + (size_t)(f * SAMPLE_NUM + s) * HIST);
    const float4* h4 = reinterpret_cast<const float4*>(hist);
    #pragma unroll
    for (int i = threadIdx.x; i < HIST / 4; i += TPB) o[i] = h4[i];
}

extern "C" void kernel_launch(void* const* d_in, const int* in_sizes, int n_in,
                              void* d_out, int out_size) {
    (void)in_sizes; (void)n_in; (void)out_size;
    const float* vals  = (const float*)d_in[0];
    const int*   idx32 = (const int*)d_in[1];   // raw view; dtype detected on device
    float*       out   = (float*)d_out;

    cudaFuncSetAttribute(accum_kernel,
                         cudaFuncAttributeMaxDynamicSharedMemorySize,
                         HIST * (int)sizeof(float));

    bins_kernel<<<NUM_EVENTS / (256 * 4), 256>>>(idx32);
    accum_kernel<<<dim3(FRAME_NUMBER, SAMPLE_NUM), TPB, HIST * sizeof(float)>>>(vals, out);
}